// round 14
// baseline (speedup 1.0000x reference)
#include <cuda_runtime.h>
#include <math.h>

#define BATCH 8
#define CHAN  128
#define HDIM  64
#define WDIM  64
#define LLEN  4096
#define NHEAD 8
#define NPTS  8
#define DHEAD 16

__device__ float g_value[BATCH * LLEN * CHAN];
__device__ float g_off  [BATCH * LLEN * NHEAD * NPTS * 2];
__device__ float g_attn [BATCH * LLEN * NHEAD * NPTS];

// ---------------------------------------------------------------------------
// Kernel 1: fused projections (R2 version — measured ~64us, near fp32 peak).
// ---------------------------------------------------------------------------
__global__ __launch_bounds__(256)
void proj_kernel(const float* __restrict__ nbr, const float* __restrict__ ext,
                 const float* __restrict__ Wv, const float* __restrict__ bv,
                 const float* __restrict__ Wo, const float* __restrict__ bo,
                 const float* __restrict__ Wa, const float* __restrict__ ba)
{
    __shared__ float As[16][128];
    __shared__ float Bs[16][64];

    const int nt  = blockIdx.y;
    const int b   = blockIdx.x >> 5;
    const int l0  = (blockIdx.x & 31) << 7;
    const int tid = threadIdx.x;
    const int tx  = tid & 15;
    const int ty  = tid >> 4;

    const float* Asrc = (nt < 2) ? nbr : ext;
    const float* Bsrc;
    int bstride, bcol;
    if (nt == 0)      { Bsrc = Wv; bstride = 128; bcol = 0;  }
    else if (nt == 1) { Bsrc = Wv; bstride = 128; bcol = 64; }
    else if (nt == 2) { Bsrc = Wo; bstride = 128; bcol = 0;  }
    else if (nt == 3) { Bsrc = Wo; bstride = 128; bcol = 64; }
    else              { Bsrc = Wa; bstride = 64;  bcol = 0;  }

    float acc[8][4];
    #pragma unroll
    for (int i = 0; i < 8; i++)
        #pragma unroll
        for (int j = 0; j < 4; j++) acc[i][j] = 0.f;

    for (int k0 = 0; k0 < CHAN; k0 += 16) {
        #pragma unroll
        for (int i = 0; i < 2; i++) {
            int fid = tid + i * 256;
            int row = fid >> 5, c4 = (fid & 31) << 2;
            *(float4*)&As[row][c4] =
                *(const float4*)&Asrc[(size_t)(b * CHAN + k0 + row) * LLEN + l0 + c4];
        }
        {
            int row = tid >> 4, c4 = (tid & 15) << 2;
            *(float4*)&Bs[row][c4] =
                *(const float4*)&Bsrc[(k0 + row) * bstride + bcol + c4];
        }
        __syncthreads();

        #pragma unroll
        for (int kk = 0; kk < 16; kk++) {
            float4 a0 = *(float4*)&As[kk][ty * 8];
            float4 a1 = *(float4*)&As[kk][ty * 8 + 4];
            float4 bb = *(float4*)&Bs[kk][tx * 4];
            float av[8] = {a0.x, a0.y, a0.z, a0.w, a1.x, a1.y, a1.z, a1.w};
            float bw[4] = {bb.x, bb.y, bb.z, bb.w};
            #pragma unroll
            for (int i = 0; i < 8; i++)
                #pragma unroll
                for (int j = 0; j < 4; j++)
                    acc[i][j] = fmaf(av[i], bw[j], acc[i][j]);
        }
        __syncthreads();
    }

    if (nt < 2) {
        int n = nt * 64 + tx * 4;
        float4 bia = *(const float4*)&bv[n];
        #pragma unroll
        for (int i = 0; i < 8; i++) {
            int l = l0 + ty * 8 + i;
            float4 v = {acc[i][0] + bia.x, acc[i][1] + bia.y,
                        acc[i][2] + bia.z, acc[i][3] + bia.w};
            *(float4*)&g_value[(size_t)(b * LLEN + l) * 128 + n] = v;
        }
    } else if (nt < 4) {
        int m = (nt - 2) * 64 + tx * 4;
        float4 bia = *(const float4*)&bo[m];
        #pragma unroll
        for (int i = 0; i < 8; i++) {
            int l = l0 + ty * 8 + i;
            float4 v = {10.0f * tanhf(acc[i][0] + bia.x), 10.0f * tanhf(acc[i][1] + bia.y),
                        10.0f * tanhf(acc[i][2] + bia.z), 10.0f * tanhf(acc[i][3] + bia.w)};
            *(float4*)&g_off[(size_t)(b * LLEN + l) * 128 + m] = v;
        }
    } else {
        int m = tx * 4;
        float4 bia = *(const float4*)&ba[m];
        #pragma unroll
        for (int i = 0; i < 8; i++) {
            int l = l0 + ty * 8 + i;
            float4 v = {acc[i][0] + bia.x, acc[i][1] + bia.y,
                        acc[i][2] + bia.z, acc[i][3] + bia.w};
            *(float4*)&g_attn[(size_t)(b * LLEN + l) * 64 + m] = v;
        }
    }
}

// ---------------------------------------------------------------------------
// Kernel 2: fused sampling + output projection.
// Phase 1 (per half of 32 l): per (l,h,p) precompute the 4 FINAL weights
//   (softmax * bilinear * validity) and a packed clamped corner index
//   idx00 | dx<<12 | dy<<13. One task per thread (256 = 32l x 8h).
// Phase 2: one warp per l. Per point: LDS128 weights + LDS32 idx (broadcast,
//   [l][p][h] layout = conflict-free), 4 LDG.128 gathers, 16 FFMA.
// Phase 3: output projection (wtile aliases staging).
// ---------------------------------------------------------------------------
#define MID_STRIDE 132
// floats: sw4 staging 32*8*8*4 = 8192 | sidx 2048 | s_mid 64*132 = 8448
#define SIDX_OFF  8192
#define SMID_OFF  10240
#define SMEM_FLOATS (10240 + 64 * MID_STRIDE)

__global__ __launch_bounds__(256, 3)
void sample_out_kernel(const float* __restrict__ Wout,
                       const float* __restrict__ bout,
                       float* __restrict__ out)
{
    extern __shared__ float sm[];
    float4* sw4  = (float4*)sm;            // [32l][8p][8h] float4 weights
    int*   sidx  = (int*)(sm + SIDX_OFF);  // [32l][8p][8h] packed idx
    float* wtile = sm;                     // aliases staging in phase 3
    float* s_mid = sm + SMID_OFF;

    const int b    = blockIdx.y;
    const int tile = blockIdx.x;
    const int x0t  = (tile & 7) * 8;
    const int y0t  = (tile >> 3) * 8;
    const int tid  = threadIdx.x;

    const int warp = tid >> 5;
    const int lane = tid & 31;
    const int hh   = lane >> 2;
    const int ch   = hh * 16 + (lane & 3) * 4;
    const float* vbase = g_value + (size_t)b * LLEN * CHAN + ch;

    #pragma unroll 1
    for (int half = 0; half < 2; half++) {
        // ---- Phase 1: 256 tasks = (32 l, 8 h) ----
        {
            int l_half = tid >> 3;
            int h      = tid & 7;
            int l_loc  = half * 32 + l_half;
            int lx = x0t + (l_loc & 7);
            int ly = y0t + (l_loc >> 3);
            size_t bl = (size_t)b * LLEN + ly * WDIM + lx;

            const float* op = g_off + bl * 128 + h * 16;
            float4 o0 = *(const float4*)(op);
            float4 o1 = *(const float4*)(op + 4);
            float4 o2 = *(const float4*)(op + 8);
            float4 o3 = *(const float4*)(op + 12);
            float ox[8] = {o0.x, o0.z, o1.x, o1.z, o2.x, o2.z, o3.x, o3.z};
            float oy[8] = {o0.y, o0.w, o1.y, o1.w, o2.y, o2.w, o3.y, o3.w};

            const float* ap = g_attn + bl * 64 + h * 8;
            float4 g0 = *(const float4*)(ap);
            float4 g1 = *(const float4*)(ap + 4);
            float lg[8] = {g0.x, g0.y, g0.z, g0.w, g1.x, g1.y, g1.z, g1.w};

            float m = -1e30f;
            #pragma unroll
            for (int p = 0; p < 8; p++) m = fmaxf(m, lg[p]);
            float e[8], s = 0.f;
            #pragma unroll
            for (int p = 0; p < 8; p++) { e[p] = __expf(lg[p] - m); s += e[p]; }
            float inv = 1.0f / s;
            float fxb = (float)lx, fyb = (float)ly;

            #pragma unroll
            for (int p = 0; p < 8; p++) {
                float wt = e[p] * inv;
                float px = fxb + ox[p];
                float py = fyb + oy[p];
                int x0 = __float2int_rd(px);
                int y0 = __float2int_rd(py);
                float fx = px - (float)x0;
                float fy = py - (float)y0;

                int xc0 = min(max(x0, 0), WDIM - 1);
                int xc1 = min(max(x0 + 1, 0), WDIM - 1);
                int yc0 = min(max(y0, 0), HDIM - 1);
                int yc1 = min(max(y0 + 1, 0), HDIM - 1);
                float mx0 = (x0 >= 0  && x0 < WDIM)      ? 1.f : 0.f;
                float mx1 = (x0 >= -1 && x0 < WDIM - 1)  ? 1.f : 0.f;
                float my0 = (y0 >= 0  && y0 < HDIM)      ? 1.f : 0.f;
                float my1 = (y0 >= -1 && y0 < HDIM - 1)  ? 1.f : 0.f;

                float gx0 = 1.f - fx, gy0 = 1.f - fy;
                float4 w;
                w.x = wt * gx0 * gy0 * mx0 * my0;
                w.y = wt * fx  * gy0 * mx1 * my0;
                w.z = wt * gx0 * fy  * mx0 * my1;
                w.w = wt * fx  * fy  * mx1 * my1;

                int pk = (yc0 * WDIM + xc0) | ((xc1 - xc0) << 12) | ((yc1 - yc0) << 13);
                int pt = (l_half * 8 + p) * 8 + h;
                sw4 [pt] = w;
                sidx[pt] = pk;
            }
        }
        __syncthreads();

        // ---- Phase 2: one warp per l ----
        #pragma unroll 1
        for (int it = 0; it < 4; it++) {
            int l_half = it * 8 + warp;
            int l_loc  = half * 32 + l_half;

            float4 acc = {0.f, 0.f, 0.f, 0.f};
            int pt0 = (l_half * 8) * 8 + hh;
            #pragma unroll
            for (int p = 0; p < 8; p++) {
                int pt = pt0 + p * 8;
                float4 w = sw4[pt];            // broadcast within head group
                int   pk = sidx[pt];

                const float* p00 = vbase + ((size_t)(pk & 4095) << 7);
                int dxo = (pk & (1 << 12)) ? CHAN : 0;
                int dyo = (pk & (1 << 13)) ? (WDIM * CHAN) : 0;
                const float* p01 = p00 + dyo;

                float4 v00 = *(const float4*)(p00);
                float4 v10 = *(const float4*)(p00 + dxo);
                float4 v01 = *(const float4*)(p01);
                float4 v11 = *(const float4*)(p01 + dxo);

                acc.x = fmaf(w.x, v00.x, fmaf(w.y, v10.x, fmaf(w.z, v01.x, fmaf(w.w, v11.x, acc.x))));
                acc.y = fmaf(w.x, v00.y, fmaf(w.y, v10.y, fmaf(w.z, v01.y, fmaf(w.w, v11.y, acc.y))));
                acc.z = fmaf(w.x, v00.z, fmaf(w.y, v10.z, fmaf(w.z, v01.z, fmaf(w.w, v11.z, acc.z))));
                acc.w = fmaf(w.x, v00.w, fmaf(w.y, v10.w, fmaf(w.z, v01.w, fmaf(w.w, v11.w, acc.w))));
            }
            *(float4*)&s_mid[l_loc * MID_STRIDE + ch] = acc;
        }
        __syncthreads();
    }

    // ---- Phase 3: output projection, 64l x 128n, k in 4 tiles of 32 ----
    const int tx = tid & 15;
    const int ty = tid >> 4;
    float oacc[8][4];
    #pragma unroll
    for (int i = 0; i < 8; i++)
        #pragma unroll
        for (int j = 0; j < 4; j++) oacc[i][j] = 0.f;

    for (int k0 = 0; k0 < CHAN; k0 += 32) {
        #pragma unroll
        for (int i = 0; i < 4; i++) {
            int fid = tid + i * 256;
            int row = fid >> 5, c4 = (fid & 31) << 2;
            *(float4*)&wtile[row * 128 + c4] =
                *(const float4*)&Wout[(k0 + row) * 128 + c4];
        }
        __syncthreads();

        #pragma unroll
        for (int kk = 0; kk < 32; kk++) {
            float a[4];
            #pragma unroll
            for (int j = 0; j < 4; j++)
                a[j] = s_mid[(tx + 16 * j) * MID_STRIDE + k0 + kk];
            float4 w0 = *(float4*)&wtile[kk * 128 + ty * 8];
            float4 w1 = *(float4*)&wtile[kk * 128 + ty * 8 + 4];
            float wv[8] = {w0.x, w0.y, w0.z, w0.w, w1.x, w1.y, w1.z, w1.w};
            #pragma unroll
            for (int i = 0; i < 8; i++)
                #pragma unroll
                for (int j = 0; j < 4; j++)
                    oacc[i][j] = fmaf(wv[i], a[j], oacc[i][j]);
        }
        __syncthreads();
    }

    #pragma unroll
    for (int i = 0; i < 8; i++) {
        int n = ty * 8 + i;
        float bb = bout[n];
        #pragma unroll
        for (int j = 0; j < 4; j++) {
            int l_loc = tx + 16 * j;
            int lx = x0t + (l_loc & 7);
            int ly = y0t + (l_loc >> 3);
            out[((size_t)(b * CHAN + n)) * LLEN + ly * WDIM + lx] = oacc[i][j] + bb;
        }
    }
}

// ---------------------------------------------------------------------------
extern "C" void kernel_launch(void* const* d_in, const int* in_sizes, int n_in,
                              void* d_out, int out_size)
{
    const float* nbr  = (const float*)d_in[0];
    const float* ext  = (const float*)d_in[1];
    const float* Wv   = (const float*)d_in[2];
    const float* bv   = (const float*)d_in[3];
    const float* Wo   = (const float*)d_in[4];
    const float* bo   = (const float*)d_in[5];
    const float* Wa   = (const float*)d_in[6];
    const float* ba   = (const float*)d_in[7];
    const float* Wout = (const float*)d_in[8];
    const float* bout = (const float*)d_in[9];
    float* out = (float*)d_out;

    static int configured = 0;
    const int smem_bytes = SMEM_FLOATS * 4;   // 74752 B
    if (!configured) {
        cudaFuncSetAttribute(sample_out_kernel,
                             cudaFuncAttributeMaxDynamicSharedMemorySize, smem_bytes);
        configured = 1;
    }

    dim3 gproj(256, 5);
    proj_kernel<<<gproj, 256>>>(nbr, ext, Wv, bv, Wo, bo, Wa, ba);

    dim3 gsamp(64, BATCH);
    sample_out_kernel<<<gsamp, 256, smem_bytes>>>(Wout, bout, out);
}

// round 16
// speedup vs baseline: 1.0123x; 1.0123x over previous
#include <cuda_runtime.h>
#include <math.h>
#include <stdint.h>

#define BATCH 8
#define CHAN  128
#define HDIM  64
#define WDIM  64
#define LLEN  4096
#define NHEAD 8
#define NPTS  8
#define DHEAD 16

__device__ float g_value[BATCH * LLEN * CHAN];
__device__ float g_off  [BATCH * LLEN * NHEAD * NPTS * 2];
__device__ float g_attn [BATCH * LLEN * NHEAD * NPTS];

__device__ __forceinline__ uint32_t f2tf32(float x) {
    uint32_t r; asm("cvt.rna.tf32.f32 %0, %1;" : "=r"(r) : "f"(x)); return r;
}
__device__ __forceinline__ void mma_tf32(float* d, const uint32_t* a,
                                         uint32_t b0, uint32_t b1) {
    asm volatile("mma.sync.aligned.m16n8k8.row.col.f32.tf32.tf32.f32 "
                 "{%0,%1,%2,%3}, {%4,%5,%6,%7}, {%8,%9}, {%0,%1,%2,%3};"
                 : "+f"(d[0]), "+f"(d[1]), "+f"(d[2]), "+f"(d[3])
                 : "r"(a[0]), "r"(a[1]), "r"(a[2]), "r"(a[3]), "r"(b0), "r"(b1));
}

// ---------------------------------------------------------------------------
// Kernel 1: fused projections via 3xTF32 tensor-core MMA.
// Block: 128 l x 64 n; 8 warps, each warp 16 l x 64 n (8 n-frags m16n8k8).
// A/B split into tf32 hi/lo at staging; D += Ah*Bh + Al*Bh + Ah*Bl.
// Pads: A rows 136, B rows 72 -> all fragment LDS conflict-free.
// ---------------------------------------------------------------------------
#define APAD 136
#define BPAD 72

__global__ __launch_bounds__(256)
void proj_kernel(const float* __restrict__ nbr, const float* __restrict__ ext,
                 const float* __restrict__ Wv, const float* __restrict__ bv,
                 const float* __restrict__ Wo, const float* __restrict__ bo,
                 const float* __restrict__ Wa, const float* __restrict__ ba)
{
    __shared__ float Ah[16][APAD], Al[16][APAD];
    __shared__ float Bh[16][BPAD], Bl[16][BPAD];

    const int nt   = blockIdx.y;
    const int b    = blockIdx.x >> 5;
    const int l0   = (blockIdx.x & 31) << 7;
    const int tid  = threadIdx.x;
    const int warp = tid >> 5;
    const int lane = tid & 31;
    const int g    = lane >> 2;    // group (row within fragment)
    const int tg   = lane & 3;     // thread-in-group (col within fragment)
    const int lw   = warp * 16;    // warp's l offset within block

    const float* Asrc = (nt < 2) ? nbr : ext;
    const float* Bsrc;
    int bstride, bcol;
    if (nt == 0)      { Bsrc = Wv; bstride = 128; bcol = 0;  }
    else if (nt == 1) { Bsrc = Wv; bstride = 128; bcol = 64; }
    else if (nt == 2) { Bsrc = Wo; bstride = 128; bcol = 0;  }
    else if (nt == 3) { Bsrc = Wo; bstride = 128; bcol = 64; }
    else              { Bsrc = Wa; bstride = 64;  bcol = 0;  }

    float acc[8][4];
    #pragma unroll
    for (int nf = 0; nf < 8; nf++)
        #pragma unroll
        for (int c = 0; c < 4; c++) acc[nf][c] = 0.f;

    for (int k0 = 0; k0 < CHAN; k0 += 16) {
        // Stage A (16 k x 128 l), split hi/lo
        #pragma unroll
        for (int i = 0; i < 2; i++) {
            int fid = tid + i * 256;
            int row = fid >> 5, c4 = (fid & 31) << 2;
            float4 v = *(const float4*)&Asrc[(size_t)(b * CHAN + k0 + row) * LLEN + l0 + c4];
            float vv[4] = {v.x, v.y, v.z, v.w};
            #pragma unroll
            for (int j = 0; j < 4; j++) {
                float hi = __uint_as_float(f2tf32(vv[j]));
                Ah[row][c4 + j] = hi;
                Al[row][c4 + j] = __uint_as_float(f2tf32(vv[j] - hi));
            }
        }
        // Stage B (16 k x 64 n), split hi/lo
        {
            int row = tid >> 4, c4 = (tid & 15) << 2;
            float4 v = *(const float4*)&Bsrc[(k0 + row) * bstride + bcol + c4];
            float vv[4] = {v.x, v.y, v.z, v.w};
            #pragma unroll
            for (int j = 0; j < 4; j++) {
                float hi = __uint_as_float(f2tf32(vv[j]));
                Bh[row][c4 + j] = hi;
                Bl[row][c4 + j] = __uint_as_float(f2tf32(vv[j] - hi));
            }
        }
        __syncthreads();

        #pragma unroll
        for (int kk = 0; kk < 2; kk++) {
            int kb = kk * 8;
            uint32_t ah[4], al[4];
            ah[0] = __float_as_uint(Ah[kb + tg    ][lw + g    ]);
            ah[1] = __float_as_uint(Ah[kb + tg    ][lw + g + 8]);
            ah[2] = __float_as_uint(Ah[kb + tg + 4][lw + g    ]);
            ah[3] = __float_as_uint(Ah[kb + tg + 4][lw + g + 8]);
            al[0] = __float_as_uint(Al[kb + tg    ][lw + g    ]);
            al[1] = __float_as_uint(Al[kb + tg    ][lw + g + 8]);
            al[2] = __float_as_uint(Al[kb + tg + 4][lw + g    ]);
            al[3] = __float_as_uint(Al[kb + tg + 4][lw + g + 8]);

            #pragma unroll
            for (int nf = 0; nf < 8; nf++) {
                uint32_t bh0 = __float_as_uint(Bh[kb + tg    ][nf * 8 + g]);
                uint32_t bh1 = __float_as_uint(Bh[kb + tg + 4][nf * 8 + g]);
                uint32_t bl0 = __float_as_uint(Bl[kb + tg    ][nf * 8 + g]);
                uint32_t bl1 = __float_as_uint(Bl[kb + tg + 4][nf * 8 + g]);
                mma_tf32(acc[nf], ah, bh0, bh1);
                mma_tf32(acc[nf], al, bh0, bh1);
                mma_tf32(acc[nf], ah, bl0, bl1);
            }
        }
        __syncthreads();
    }

    // Epilogue. Lane owns (l = l0+lw+g / +8, n_local = nf*8 + tg*2, +1).
    const int lA = l0 + lw + g;
    const int lB = lA + 8;
    if (nt < 2) {
        #pragma unroll
        for (int nf = 0; nf < 8; nf++) {
            int n = nt * 64 + nf * 8 + tg * 2;
            float b0 = bv[n], b1 = bv[n + 1];
            *(float2*)&g_value[(size_t)(b * LLEN + lA) * 128 + n] =
                make_float2(acc[nf][0] + b0, acc[nf][1] + b1);
            *(float2*)&g_value[(size_t)(b * LLEN + lB) * 128 + n] =
                make_float2(acc[nf][2] + b0, acc[nf][3] + b1);
        }
    } else if (nt < 4) {
        #pragma unroll
        for (int nf = 0; nf < 8; nf++) {
            int m = (nt - 2) * 64 + nf * 8 + tg * 2;
            float b0 = bo[m], b1 = bo[m + 1];
            *(float2*)&g_off[(size_t)(b * LLEN + lA) * 128 + m] =
                make_float2(10.0f * tanhf(acc[nf][0] + b0), 10.0f * tanhf(acc[nf][1] + b1));
            *(float2*)&g_off[(size_t)(b * LLEN + lB) * 128 + m] =
                make_float2(10.0f * tanhf(acc[nf][2] + b0), 10.0f * tanhf(acc[nf][3] + b1));
        }
    } else {
        #pragma unroll
        for (int nf = 0; nf < 8; nf++) {
            int m = nf * 8 + tg * 2;
            float b0 = ba[m], b1 = ba[m + 1];
            *(float2*)&g_attn[(size_t)(b * LLEN + lA) * 64 + m] =
                make_float2(acc[nf][0] + b0, acc[nf][1] + b1);
            *(float2*)&g_attn[(size_t)(b * LLEN + lB) * 64 + m] =
                make_float2(acc[nf][2] + b0, acc[nf][3] + b1);
        }
    }
}

// ---------------------------------------------------------------------------
// Kernel 2: fused softmax + sampling + output projection — EXACT R4 version
// (measured 75.5us; every redesign since has regressed).
// ---------------------------------------------------------------------------
#define MID_STRIDE 132

__global__ __launch_bounds__(256)
void sample_out_kernel(const float* __restrict__ Wout,
                       const float* __restrict__ bout,
                       float* __restrict__ out)
{
    extern __shared__ float sm[];
    float* sw    = sm;                    // 4096
    float* spx   = sm + 4096;             // 4096
    float* spy   = sm + 8192;             // 4096
    float* s_mid = sm + 12288;            // 64*132 = 8448
    float* wtile = sm + 12288 + 8448;     // 32*128 = 4096

    const int b    = blockIdx.y;
    const int tile = blockIdx.x;
    const int x0t  = (tile & 7) * 8;
    const int y0t  = (tile >> 3) * 8;
    const int tid  = threadIdx.x;

    // ---- Phase 1: softmax + absolute sample coords ----
    #pragma unroll
    for (int i = 0; i < 2; i++) {
        int task  = tid + i * 256;
        int l_loc = task >> 3;
        int h     = task & 7;
        int lx = x0t + (l_loc & 7);
        int ly = y0t + (l_loc >> 3);
        size_t bl = (size_t)b * LLEN + ly * WDIM + lx;

        const float* op = g_off + bl * 128 + h * 16;
        float4 o0 = *(const float4*)(op);
        float4 o1 = *(const float4*)(op + 4);
        float4 o2 = *(const float4*)(op + 8);
        float4 o3 = *(const float4*)(op + 12);
        float ox[8] = {o0.x, o0.z, o1.x, o1.z, o2.x, o2.z, o3.x, o3.z};
        float oy[8] = {o0.y, o0.w, o1.y, o1.w, o2.y, o2.w, o3.y, o3.w};

        const float* ap = g_attn + bl * 64 + h * 8;
        float4 g0 = *(const float4*)(ap);
        float4 g1 = *(const float4*)(ap + 4);
        float lg[8] = {g0.x, g0.y, g0.z, g0.w, g1.x, g1.y, g1.z, g1.w};

        float m = -1e30f;
        #pragma unroll
        for (int p = 0; p < 8; p++) m = fmaxf(m, lg[p]);
        float e[8], s = 0.f;
        #pragma unroll
        for (int p = 0; p < 8; p++) { e[p] = __expf(lg[p] - m); s += e[p]; }
        float inv = 1.0f / s;

        int base = l_loc * 64 + h * 8;
        #pragma unroll
        for (int p = 0; p < 8; p++) {
            sw [base + p] = e[p] * inv;
            spx[base + p] = (float)lx + ox[p];
            spy[base + p] = (float)ly + oy[p];
        }
    }
    __syncthreads();

    // ---- Phase 2: one warp per l, float4 gathers ----
    const int warp = tid >> 5;
    const int lane = tid & 31;
    const int h    = lane >> 2;
    const int ch   = h * 16 + (lane & 3) * 4;
    const float* vbase = g_value + (size_t)b * LLEN * CHAN + ch;

    #pragma unroll 1
    for (int it = 0; it < 8; it++) {
        int l_loc = it * 8 + warp;
        int lx = x0t + (l_loc & 7);
        int ly = y0t + (l_loc >> 3);

        float4 acc = {0.f, 0.f, 0.f, 0.f};
        int sbase = l_loc * 64 + h * 8;
        #pragma unroll
        for (int p = 0; p < 8; p++) {
            float wt = sw [sbase + p];
            float px = spx[sbase + p];
            float py = spy[sbase + p];
            float x0f = floorf(px), y0f = floorf(py);
            float fx = px - x0f, fy = py - y0f;
            int x0 = (int)x0f, y0 = (int)y0f;

            int xc0 = min(max(x0, 0), WDIM - 1);
            int xc1 = min(max(x0 + 1, 0), WDIM - 1);
            int yc0 = min(max(y0, 0), HDIM - 1);
            int yc1 = min(max(y0 + 1, 0), HDIM - 1);
            float mx0 = (x0 >= 0  && x0 < WDIM)      ? 1.f : 0.f;
            float mx1 = (x0 >= -1 && x0 < WDIM - 1)  ? 1.f : 0.f;
            float my0 = (y0 >= 0  && y0 < HDIM)      ? 1.f : 0.f;
            float my1 = (y0 >= -1 && y0 < HDIM - 1)  ? 1.f : 0.f;

            float gx0 = 1.f - fx, gy0 = 1.f - fy;
            float w00 = wt * gx0 * gy0 * mx0 * my0;
            float w10 = wt * fx  * gy0 * mx1 * my0;
            float w01 = wt * gx0 * fy  * mx0 * my1;
            float w11 = wt * fx  * fy  * mx1 * my1;

            int r0 = yc0 * WDIM, r1 = yc1 * WDIM;
            float4 v00 = *(const float4*)(vbase + (size_t)(r0 + xc0) * CHAN);
            float4 v10 = *(const float4*)(vbase + (size_t)(r0 + xc1) * CHAN);
            float4 v01 = *(const float4*)(vbase + (size_t)(r1 + xc0) * CHAN);
            float4 v11 = *(const float4*)(vbase + (size_t)(r1 + xc1) * CHAN);

            acc.x = fmaf(w00, v00.x, fmaf(w10, v10.x, fmaf(w01, v01.x, fmaf(w11, v11.x, acc.x))));
            acc.y = fmaf(w00, v00.y, fmaf(w10, v10.y, fmaf(w01, v01.y, fmaf(w11, v11.y, acc.y))));
            acc.z = fmaf(w00, v00.z, fmaf(w10, v10.z, fmaf(w01, v01.z, fmaf(w11, v11.z, acc.z))));
            acc.w = fmaf(w00, v00.w, fmaf(w10, v10.w, fmaf(w01, v01.w, fmaf(w11, v11.w, acc.w))));
        }
        *(float4*)&s_mid[l_loc * MID_STRIDE + ch] = acc;
    }
    __syncthreads();

    // ---- Phase 3: output projection, 64l x 128n, k in 4 tiles of 32 ----
    const int tx = tid & 15;
    const int ty = tid >> 4;
    float oacc[8][4];
    #pragma unroll
    for (int i = 0; i < 8; i++)
        #pragma unroll
        for (int j = 0; j < 4; j++) oacc[i][j] = 0.f;

    for (int k0 = 0; k0 < CHAN; k0 += 32) {
        #pragma unroll
        for (int i = 0; i < 4; i++) {
            int fid = tid + i * 256;
            int row = fid >> 5, c4 = (fid & 31) << 2;
            *(float4*)&wtile[row * 128 + c4] =
                *(const float4*)&Wout[(k0 + row) * 128 + c4];
        }
        __syncthreads();

        #pragma unroll
        for (int kk = 0; kk < 32; kk++) {
            float a[4];
            #pragma unroll
            for (int j = 0; j < 4; j++)
                a[j] = s_mid[(tx + 16 * j) * MID_STRIDE + k0 + kk];
            float4 w0 = *(float4*)&wtile[kk * 128 + ty * 8];
            float4 w1 = *(float4*)&wtile[kk * 128 + ty * 8 + 4];
            float wv[8] = {w0.x, w0.y, w0.z, w0.w, w1.x, w1.y, w1.z, w1.w};
            #pragma unroll
            for (int i = 0; i < 8; i++)
                #pragma unroll
                for (int j = 0; j < 4; j++)
                    oacc[i][j] = fmaf(wv[i], a[j], oacc[i][j]);
        }
        __syncthreads();
    }

    #pragma unroll
    for (int i = 0; i < 8; i++) {
        int n = ty * 8 + i;
        float bb = bout[n];
        #pragma unroll
        for (int j = 0; j < 4; j++) {
            int l_loc = tx + 16 * j;
            int lx = x0t + (l_loc & 7);
            int ly = y0t + (l_loc >> 3);
            out[((size_t)(b * CHAN + n)) * LLEN + ly * WDIM + lx] = oacc[i][j] + bb;
        }
    }
}

// ---------------------------------------------------------------------------
extern "C" void kernel_launch(void* const* d_in, const int* in_sizes, int n_in,
                              void* d_out, int out_size)
{
    const float* nbr  = (const float*)d_in[0];
    const float* ext  = (const float*)d_in[1];
    const float* Wv   = (const float*)d_in[2];
    const float* bv   = (const float*)d_in[3];
    const float* Wo   = (const float*)d_in[4];
    const float* bo   = (const float*)d_in[5];
    const float* Wa   = (const float*)d_in[6];
    const float* ba   = (const float*)d_in[7];
    const float* Wout = (const float*)d_in[8];
    const float* bout = (const float*)d_in[9];
    float* out = (float*)d_out;

    static int configured = 0;
    const int smem_bytes = (12288 + 8448 + 4096) * 4;   // 99328 B
    if (!configured) {
        cudaFuncSetAttribute(sample_out_kernel,
                             cudaFuncAttributeMaxDynamicSharedMemorySize, smem_bytes);
        configured = 1;
    }

    dim3 gproj(256, 5);
    proj_kernel<<<gproj, 256>>>(nbr, ext, Wv, bv, Wo, bo, Wa, ba);

    dim3 gsamp(64, BATCH);
    sample_out_kernel<<<gsamp, 256, smem_bytes>>>(Wout, bout, out);
}

// round 17
// speedup vs baseline: 1.0534x; 1.0407x over previous
#include <cuda_runtime.h>
#include <math.h>

#define BATCH 8
#define CHAN  128
#define HDIM  64
#define WDIM  64
#define LLEN  4096
#define NHEAD 8
#define NPTS  8
#define DHEAD 16

__device__ float g_value[BATCH * LLEN * CHAN];
__device__ float g_off  [BATCH * LLEN * NHEAD * NPTS * 2];
__device__ float g_attn [BATCH * LLEN * NHEAD * NPTS];

// ---------------------------------------------------------------------------
// Kernel 1: fused projections (R2 math) + double-buffered smem staging.
// 128l x 64n tile, 256 thr, 8x4 per thread. Prefetch tile k+1 into regs
// during compute of tile k; STS to alternate buffer; one sync per k-tile.
// ---------------------------------------------------------------------------
__global__ __launch_bounds__(256, 3)
void proj_kernel(const float* __restrict__ nbr, const float* __restrict__ ext,
                 const float* __restrict__ Wv, const float* __restrict__ bv,
                 const float* __restrict__ Wo, const float* __restrict__ bo,
                 const float* __restrict__ Wa, const float* __restrict__ ba)
{
    __shared__ float As[2][16][128];
    __shared__ float Bs[2][16][64];

    const int nt  = blockIdx.y;
    const int b   = blockIdx.x >> 5;
    const int l0  = (blockIdx.x & 31) << 7;
    const int tid = threadIdx.x;
    const int tx  = tid & 15;
    const int ty  = tid >> 4;

    const float* Asrc = (nt < 2) ? nbr : ext;
    const float* Bsrc;
    int bstride, bcol;
    if (nt == 0)      { Bsrc = Wv; bstride = 128; bcol = 0;  }
    else if (nt == 1) { Bsrc = Wv; bstride = 128; bcol = 64; }
    else if (nt == 2) { Bsrc = Wo; bstride = 128; bcol = 0;  }
    else if (nt == 3) { Bsrc = Wo; bstride = 128; bcol = 64; }
    else              { Bsrc = Wa; bstride = 64;  bcol = 0;  }

    // staging indices (fixed per thread)
    const int ar0 = tid >> 5;                 // 0..7
    const int ar1 = (tid + 256) >> 5;         // 8..15
    const int ac  = (tid & 31) << 2;
    const int br  = tid >> 4;                 // 0..15
    const int bc  = (tid & 15) << 2;

    const float* aptr = Asrc + (size_t)b * CHAN * LLEN + l0;
    const float* bptr = Bsrc + bcol;

    float acc[8][4];
    #pragma unroll
    for (int i = 0; i < 8; i++)
        #pragma unroll
        for (int j = 0; j < 4; j++) acc[i][j] = 0.f;

    // preload tile 0
    *(float4*)&As[0][ar0][ac] = *(const float4*)&aptr[(size_t)ar0 * LLEN + ac];
    *(float4*)&As[0][ar1][ac] = *(const float4*)&aptr[(size_t)ar1 * LLEN + ac];
    *(float4*)&Bs[0][br][bc]  = *(const float4*)&bptr[br * bstride + bc];
    __syncthreads();

    #pragma unroll 1
    for (int kt = 0; kt < 8; kt++) {
        const int cur = kt & 1;

        // prefetch next tile into registers (overlaps with compute below)
        float4 pa0, pa1, pb;
        if (kt < 7) {
            const float* ap = aptr + (size_t)(kt + 1) * 16 * LLEN;
            const float* bp = bptr + (kt + 1) * 16 * bstride;
            pa0 = *(const float4*)&ap[(size_t)ar0 * LLEN + ac];
            pa1 = *(const float4*)&ap[(size_t)ar1 * LLEN + ac];
            pb  = *(const float4*)&bp[br * bstride + bc];
        }

        #pragma unroll
        for (int kk = 0; kk < 16; kk++) {
            float4 a0 = *(float4*)&As[cur][kk][ty * 8];
            float4 a1 = *(float4*)&As[cur][kk][ty * 8 + 4];
            float4 bb = *(float4*)&Bs[cur][kk][tx * 4];
            float av[8] = {a0.x, a0.y, a0.z, a0.w, a1.x, a1.y, a1.z, a1.w};
            float bw[4] = {bb.x, bb.y, bb.z, bb.w};
            #pragma unroll
            for (int i = 0; i < 8; i++)
                #pragma unroll
                for (int j = 0; j < 4; j++)
                    acc[i][j] = fmaf(av[i], bw[j], acc[i][j]);
        }

        if (kt < 7) {
            *(float4*)&As[cur ^ 1][ar0][ac] = pa0;
            *(float4*)&As[cur ^ 1][ar1][ac] = pa1;
            *(float4*)&Bs[cur ^ 1][br][bc]  = pb;
        }
        __syncthreads();
    }

    if (nt < 2) {
        int n = nt * 64 + tx * 4;
        float4 bia = *(const float4*)&bv[n];
        #pragma unroll
        for (int i = 0; i < 8; i++) {
            int l = l0 + ty * 8 + i;
            float4 v = {acc[i][0] + bia.x, acc[i][1] + bia.y,
                        acc[i][2] + bia.z, acc[i][3] + bia.w};
            *(float4*)&g_value[(size_t)(b * LLEN + l) * 128 + n] = v;
        }
    } else if (nt < 4) {
        int m = (nt - 2) * 64 + tx * 4;
        float4 bia = *(const float4*)&bo[m];
        #pragma unroll
        for (int i = 0; i < 8; i++) {
            int l = l0 + ty * 8 + i;
            float4 v = {10.0f * tanhf(acc[i][0] + bia.x), 10.0f * tanhf(acc[i][1] + bia.y),
                        10.0f * tanhf(acc[i][2] + bia.z), 10.0f * tanhf(acc[i][3] + bia.w)};
            *(float4*)&g_off[(size_t)(b * LLEN + l) * 128 + m] = v;
        }
    } else {
        int m = tx * 4;
        float4 bia = *(const float4*)&ba[m];
        #pragma unroll
        for (int i = 0; i < 8; i++) {
            int l = l0 + ty * 8 + i;
            float4 v = {acc[i][0] + bia.x, acc[i][1] + bia.y,
                        acc[i][2] + bia.z, acc[i][3] + bia.w};
            *(float4*)&g_attn[(size_t)(b * LLEN + l) * 64 + m] = v;
        }
    }
}

// ---------------------------------------------------------------------------
// Kernel 2: fused softmax + sampling + output projection — EXACT R4 code,
// with __launch_bounds__(256,3) to lift occupancy from 2 to 3 CTAs/SM.
// ---------------------------------------------------------------------------
#define MID_STRIDE 132

__global__ __launch_bounds__(256, 3)
void sample_out_kernel(const float* __restrict__ Wout,
                       const float* __restrict__ bout,
                       float* __restrict__ out)
{
    extern __shared__ float sm[];
    float* sw    = sm;                    // 4096
    float* spx   = sm + 4096;             // 4096
    float* spy   = sm + 8192;             // 4096
    float* s_mid = sm + 12288;            // 64*132 = 8448
    float* wtile = sm + 12288 + 8448;     // 32*128 = 4096

    const int b    = blockIdx.y;
    const int tile = blockIdx.x;
    const int x0t  = (tile & 7) * 8;
    const int y0t  = (tile >> 3) * 8;
    const int tid  = threadIdx.x;

    // ---- Phase 1: softmax + absolute sample coords ----
    #pragma unroll
    for (int i = 0; i < 2; i++) {
        int task  = tid + i * 256;
        int l_loc = task >> 3;
        int h     = task & 7;
        int lx = x0t + (l_loc & 7);
        int ly = y0t + (l_loc >> 3);
        size_t bl = (size_t)b * LLEN + ly * WDIM + lx;

        const float* op = g_off + bl * 128 + h * 16;
        float4 o0 = *(const float4*)(op);
        float4 o1 = *(const float4*)(op + 4);
        float4 o2 = *(const float4*)(op + 8);
        float4 o3 = *(const float4*)(op + 12);
        float ox[8] = {o0.x, o0.z, o1.x, o1.z, o2.x, o2.z, o3.x, o3.z};
        float oy[8] = {o0.y, o0.w, o1.y, o1.w, o2.y, o2.w, o3.y, o3.w};

        const float* ap = g_attn + bl * 64 + h * 8;
        float4 g0 = *(const float4*)(ap);
        float4 g1 = *(const float4*)(ap + 4);
        float lg[8] = {g0.x, g0.y, g0.z, g0.w, g1.x, g1.y, g1.z, g1.w};

        float m = -1e30f;
        #pragma unroll
        for (int p = 0; p < 8; p++) m = fmaxf(m, lg[p]);
        float e[8], s = 0.f;
        #pragma unroll
        for (int p = 0; p < 8; p++) { e[p] = __expf(lg[p] - m); s += e[p]; }
        float inv = 1.0f / s;

        int base = l_loc * 64 + h * 8;
        #pragma unroll
        for (int p = 0; p < 8; p++) {
            sw [base + p] = e[p] * inv;
            spx[base + p] = (float)lx + ox[p];
            spy[base + p] = (float)ly + oy[p];
        }
    }
    __syncthreads();

    // ---- Phase 2: one warp per l, float4 gathers ----
    const int warp = tid >> 5;
    const int lane = tid & 31;
    const int h    = lane >> 2;
    const int ch   = h * 16 + (lane & 3) * 4;
    const float* vbase = g_value + (size_t)b * LLEN * CHAN + ch;

    #pragma unroll 1
    for (int it = 0; it < 8; it++) {
        int l_loc = it * 8 + warp;
        int lx = x0t + (l_loc & 7);
        int ly = y0t + (l_loc >> 3);

        float4 acc = {0.f, 0.f, 0.f, 0.f};
        int sbase = l_loc * 64 + h * 8;
        #pragma unroll
        for (int p = 0; p < 8; p++) {
            float wt = sw [sbase + p];
            float px = spx[sbase + p];
            float py = spy[sbase + p];
            float x0f = floorf(px), y0f = floorf(py);
            float fx = px - x0f, fy = py - y0f;
            int x0 = (int)x0f, y0 = (int)y0f;

            int xc0 = min(max(x0, 0), WDIM - 1);
            int xc1 = min(max(x0 + 1, 0), WDIM - 1);
            int yc0 = min(max(y0, 0), HDIM - 1);
            int yc1 = min(max(y0 + 1, 0), HDIM - 1);
            float mx0 = (x0 >= 0  && x0 < WDIM)      ? 1.f : 0.f;
            float mx1 = (x0 >= -1 && x0 < WDIM - 1)  ? 1.f : 0.f;
            float my0 = (y0 >= 0  && y0 < HDIM)      ? 1.f : 0.f;
            float my1 = (y0 >= -1 && y0 < HDIM - 1)  ? 1.f : 0.f;

            float gx0 = 1.f - fx, gy0 = 1.f - fy;
            float w00 = wt * gx0 * gy0 * mx0 * my0;
            float w10 = wt * fx  * gy0 * mx1 * my0;
            float w01 = wt * gx0 * fy  * mx0 * my1;
            float w11 = wt * fx  * fy  * mx1 * my1;

            int r0 = yc0 * WDIM, r1 = yc1 * WDIM;
            float4 v00 = *(const float4*)(vbase + (size_t)(r0 + xc0) * CHAN);
            float4 v10 = *(const float4*)(vbase + (size_t)(r0 + xc1) * CHAN);
            float4 v01 = *(const float4*)(vbase + (size_t)(r1 + xc0) * CHAN);
            float4 v11 = *(const float4*)(vbase + (size_t)(r1 + xc1) * CHAN);

            acc.x = fmaf(w00, v00.x, fmaf(w10, v10.x, fmaf(w01, v01.x, fmaf(w11, v11.x, acc.x))));
            acc.y = fmaf(w00, v00.y, fmaf(w10, v10.y, fmaf(w01, v01.y, fmaf(w11, v11.y, acc.y))));
            acc.z = fmaf(w00, v00.z, fmaf(w10, v10.z, fmaf(w01, v01.z, fmaf(w11, v11.z, acc.z))));
            acc.w = fmaf(w00, v00.w, fmaf(w10, v10.w, fmaf(w01, v01.w, fmaf(w11, v11.w, acc.w))));
        }
        *(float4*)&s_mid[l_loc * MID_STRIDE + ch] = acc;
    }
    __syncthreads();

    // ---- Phase 3: output projection, 64l x 128n, k in 4 tiles of 32 ----
    const int tx = tid & 15;
    const int ty = tid >> 4;
    float oacc[8][4];
    #pragma unroll
    for (int i = 0; i < 8; i++)
        #pragma unroll
        for (int j = 0; j < 4; j++) oacc[i][j] = 0.f;

    for (int k0 = 0; k0 < CHAN; k0 += 32) {
        #pragma unroll
        for (int i = 0; i < 4; i++) {
            int fid = tid + i * 256;
            int row = fid >> 5, c4 = (fid & 31) << 2;
            *(float4*)&wtile[row * 128 + c4] =
                *(const float4*)&Wout[(k0 + row) * 128 + c4];
        }
        __syncthreads();

        #pragma unroll
        for (int kk = 0; kk < 32; kk++) {
            float a[4];
            #pragma unroll
            for (int j = 0; j < 4; j++)
                a[j] = s_mid[(tx + 16 * j) * MID_STRIDE + k0 + kk];
            float4 w0 = *(float4*)&wtile[kk * 128 + ty * 8];
            float4 w1 = *(float4*)&wtile[kk * 128 + ty * 8 + 4];
            float wv[8] = {w0.x, w0.y, w0.z, w0.w, w1.x, w1.y, w1.z, w1.w};
            #pragma unroll
            for (int i = 0; i < 8; i++)
                #pragma unroll
                for (int j = 0; j < 4; j++)
                    oacc[i][j] = fmaf(wv[i], a[j], oacc[i][j]);
        }
        __syncthreads();
    }

    #pragma unroll
    for (int i = 0; i < 8; i++) {
        int n = ty * 8 + i;
        float bb = bout[n];
        #pragma unroll
        for (int j = 0; j < 4; j++) {
            int l_loc = tx + 16 * j;
            int lx = x0t + (l_loc & 7);
            int ly = y0t + (l_loc >> 3);
            out[((size_t)(b * CHAN + n)) * LLEN + ly * WDIM + lx] = oacc[i][j] + bb;
        }
    }
}

// ---------------------------------------------------------------------------
extern "C" void kernel_launch(void* const* d_in, const int* in_sizes, int n_in,
                              void* d_out, int out_size)
{
    const float* nbr  = (const float*)d_in[0];
    const float* ext  = (const float*)d_in[1];
    const float* Wv   = (const float*)d_in[2];
    const float* bv   = (const float*)d_in[3];
    const float* Wo   = (const float*)d_in[4];
    const float* bo   = (const float*)d_in[5];
    const float* Wa   = (const float*)d_in[6];
    const float* ba   = (const float*)d_in[7];
    const float* Wout = (const float*)d_in[8];
    const float* bout = (const float*)d_in[9];
    float* out = (float*)d_out;

    static int configured = 0;
    const int smem_bytes = (12288 + 8448 + 4096) * 4;   // 99328 B
    if (!configured) {
        cudaFuncSetAttribute(sample_out_kernel,
                             cudaFuncAttributeMaxDynamicSharedMemorySize, smem_bytes);
        configured = 1;
    }

    dim3 gproj(256, 5);
    proj_kernel<<<gproj, 256>>>(nbr, ext, Wv, bv, Wo, bo, Wa, ba);

    dim3 gsamp(64, BATCH);
    sample_out_kernel<<<gsamp, 256, smem_bytes>>>(Wout, bout, out);
}